// round 2
// baseline (speedup 1.0000x reference)
#include <cuda_runtime.h>
#include <math.h>

// Problem-fixed sizes: N=100000, E=1600000, D=128, EIG=32.
#define MAXN 100000
#define MAXE 1600000

// Scratch (device globals — no allocation allowed).
__device__ float g_me[MAXN];        // per-node motif embedding value
__device__ int   g_cnt[MAXN];       // histogram, then scatter cursor
__device__ int   g_off[MAXN + 1];   // CSR row offsets
__device__ float g_acc[3];          // sum(ab), sum(a2), sum(b2)
__device__ float g_par[2];          // [0]=exp(lambda0), [1]=c = gamma*sim
__device__ int2  g_edge[MAXE];      // (col, adj-as-int) sorted by row

// ---------------------------------------------------------------------------
// K0: zero counters/accumulators, compute me[n] = motif_emb_w[motif_ids[n]]
// ---------------------------------------------------------------------------
__global__ void k_init(const float* __restrict__ memb,
                       const int* __restrict__ mids, int n) {
    int i = blockIdx.x * blockDim.x + threadIdx.x;
    if (i == 0) { g_acc[0] = 0.f; g_acc[1] = 0.f; g_acc[2] = 0.f; }
    if (i < n) {
        g_me[i]  = memb[mids[i]];
        g_cnt[i] = 0;
    }
}

// ---------------------------------------------------------------------------
// K1: edge-level scalar reductions (for cosine sim) + row histogram
// ---------------------------------------------------------------------------
__global__ void k_edge1(const int* __restrict__ row,
                        const int* __restrict__ col, int e) {
    float pab = 0.f, pa2 = 0.f, pb2 = 0.f;
    for (int i = blockIdx.x * blockDim.x + threadIdx.x; i < e;
         i += gridDim.x * blockDim.x) {
        int r = row[i], c = col[i];
        atomicAdd(&g_cnt[r], 1);
        float a = g_me[r], b = g_me[c];
        pab = fmaf(a, b, pab);
        pa2 = fmaf(a, a, pa2);
        pb2 = fmaf(b, b, pb2);
    }
#pragma unroll
    for (int o = 16; o; o >>= 1) {
        pab += __shfl_down_sync(0xffffffffu, pab, o);
        pa2 += __shfl_down_sync(0xffffffffu, pa2, o);
        pb2 += __shfl_down_sync(0xffffffffu, pb2, o);
    }
    __shared__ float sb[3][8];
    int w = threadIdx.x >> 5, l = threadIdx.x & 31;
    if (!l) { sb[0][w] = pab; sb[1][w] = pa2; sb[2][w] = pb2; }
    __syncthreads();
    if (!threadIdx.x) {
        float t0 = 0.f, t1 = 0.f, t2 = 0.f;
        int nw = blockDim.x >> 5;
        for (int j = 0; j < nw; j++) { t0 += sb[0][j]; t1 += sb[1][j]; t2 += sb[2][j]; }
        atomicAdd(&g_acc[0], t0);
        atomicAdd(&g_acc[1], t1);
        atomicAdd(&g_acc[2], t2);
    }
}

// ---------------------------------------------------------------------------
// K2: exclusive scan of histogram -> CSR offsets + cursor; compute scalars
// ---------------------------------------------------------------------------
__global__ void k_scan(const float* __restrict__ lambda0,
                       const float* __restrict__ gamma, int n, int e) {
    __shared__ int ssum[1024];
    int t = threadIdx.x;
    int chunk = (n + 1023) / 1024;
    int b = t * chunk;
    int en = b + chunk; if (en > n) en = n;
    int s = 0;
    for (int i = b; i < en; i++) s += g_cnt[i];
    ssum[t] = s;
    __syncthreads();
    if (!t) {
        int run = 0;
        for (int i = 0; i < 1024; i++) { int v = ssum[i]; ssum[i] = run; run += v; }
        g_off[n] = e;
        float sab = g_acc[0], sa2 = g_acc[1], sb2 = g_acc[2];
        float na = fmaxf(sqrtf(sa2), 1e-8f);
        float nb = fmaxf(sqrtf(sb2), 1e-8f);
        g_par[0] = expf(lambda0[0]);
        g_par[1] = gamma[0] * (sab / (na * nb));
    }
    __syncthreads();
    int run = ssum[t];
    for (int i = b; i < en; i++) {
        int v = g_cnt[i];
        g_off[i] = run;
        g_cnt[i] = run;  // cursor for the scatter pass
        run += v;
    }
}

// ---------------------------------------------------------------------------
// K3: counting-sort scatter of packed (col, adj) into row-sorted order.
// Packed int2 write: one 8B scattered store per edge instead of two 4B ones.
// ---------------------------------------------------------------------------
__global__ void k_scatter(const int* __restrict__ row,
                          const int* __restrict__ col,
                          const float* __restrict__ adj, int e) {
    for (int i = blockIdx.x * blockDim.x + threadIdx.x; i < e;
         i += gridDim.x * blockDim.x) {
        int pos = atomicAdd(&g_cnt[row[i]], 1);
        g_edge[pos] = make_int2(col[i], __float_as_int(adj[i]));
    }
}

// ---------------------------------------------------------------------------
// K4: single-pass fused kernel. One warp per destination row.
// Online (flash-style) dual softmax: per edge, gather k/eigs/v together,
// warp-reduce the score, and update (m,z,acc) for both branches.
// Lane l owns float4 l of the 128-dim vectors and eig component l (EIG=32).
// ---------------------------------------------------------------------------
__global__ void __launch_bounds__(256)
k_main(const float4* __restrict__ q4, const float4* __restrict__ k4p,
       const float4* __restrict__ v4p, const float* __restrict__ eigs,
       float4* __restrict__ out4, int n) {
    int wid  = (blockIdx.x * blockDim.x + threadIdx.x) >> 5;
    int lane = threadIdx.x & 31;
    if (wid >= n) return;
    int start = g_off[wid];
    int end   = g_off[wid + 1];
    float4 zero = make_float4(0.f, 0.f, 0.f, 0.f);
    if (start == end) {  // empty segment -> zeros (matches segment_sum)
        out4[wid * 32 + lane] = zero;
        return;
    }
    float lambda = g_par[0];
    float c      = g_par[1];
    const float inv = 0.08838834764831845f;  // 1/sqrt(128)

    float4 q  = q4[wid * 32 + lane];
    float  er = eigs[wid * 32 + lane];

    float  m0 = -3.4e38f, z0 = 0.f;
    float  m1 = -3.4e38f, z1 = 0.f;
    float4 a0 = zero, a1 = zero;

    for (int base = start; base < end; base += 32) {
        int nb = end - base; if (nb > 32) nb = 32;
        // one coalesced load covers up to 32 edges of (col, adj)
        int2 ea = (lane < nb) ? g_edge[base + lane] : make_int2(0, 0);
        int   bc = ea.x;
        float ba = __int_as_float(ea.y);

        // software pipeline: stage loads for edge i+1 while processing i
        int    ci = __shfl_sync(0xffffffffu, bc, 0);
        float4 kk = k4p[ci * 32 + lane];
        float  ec = eigs[ci * 32 + lane];
        float4 vv = v4p[ci * 32 + lane];

        for (int i = 0; i < nb; i++) {
            int j = i + 1; if (j >= nb) j = i;
            int    cn  = __shfl_sync(0xffffffffu, bc, j);
            float  adj = __shfl_sync(0xffffffffu, ba, i);
            float4 kk2 = k4p[cn * 32 + lane];
            float  ec2 = eigs[cn * 32 + lane];
            float4 vv2 = v4p[cn * 32 + lane];

            float part = fmaf(q.x, kk.x,
                         fmaf(q.y, kk.y,
                         fmaf(q.z, kk.z, q.w * kk.w))) * inv
                       + lambda * (er * ec);
#pragma unroll
            for (int o = 16; o; o >>= 1)
                part += __shfl_xor_sync(0xffffffffu, part, o);

            // branch 0: online softmax of s0
            float nm0 = fmaxf(m0, part);
            float sc0 = __expf(m0 - nm0);
            float w0  = __expf(part - nm0);
            z0   = fmaf(z0, sc0, w0);
            a0.x = fmaf(a0.x, sc0, w0 * vv.x);
            a0.y = fmaf(a0.y, sc0, w0 * vv.y);
            a0.z = fmaf(a0.z, sc0, w0 * vv.z);
            a0.w = fmaf(a0.w, sc0, w0 * vv.w);
            m0 = nm0;

            // branch 1: online softmax of c*adj
            float s1  = c * adj;
            float nm1 = fmaxf(m1, s1);
            float sc1 = __expf(m1 - nm1);
            float w1  = __expf(s1 - nm1);
            z1   = fmaf(z1, sc1, w1);
            a1.x = fmaf(a1.x, sc1, w1 * vv.x);
            a1.y = fmaf(a1.y, sc1, w1 * vv.y);
            a1.z = fmaf(a1.z, sc1, w1 * vv.z);
            a1.w = fmaf(a1.w, sc1, w1 * vv.w);
            m1 = nm1;

            kk = kk2; ec = ec2; vv = vv2;
        }
    }

    float i0 = 0.5f / z0;
    float i1 = 0.5f / z1;
    float4 o;
    o.x = fmaf(a0.x, i0, a1.x * i1);
    o.y = fmaf(a0.y, i0, a1.y * i1);
    o.z = fmaf(a0.z, i0, a1.z * i1);
    o.w = fmaf(a0.w, i0, a1.w * i1);
    out4[wid * 32 + lane] = o;
}

// ---------------------------------------------------------------------------
extern "C" void kernel_launch(void* const* d_in, const int* in_sizes, int n_in,
                              void* d_out, int out_size) {
    const float* q       = (const float*)d_in[0];
    const float* k       = (const float*)d_in[1];
    const float* v       = (const float*)d_in[2];
    const float* eigs    = (const float*)d_in[3];
    const float* adj     = (const float*)d_in[4];
    const float* lambda0 = (const float*)d_in[5];
    const float* gamma   = (const float*)d_in[6];
    const float* memb    = (const float*)d_in[7];
    const int*   row     = (const int*)d_in[8];
    const int*   col     = (const int*)d_in[9];
    const int*   mids    = (const int*)d_in[10];

    int n = in_sizes[10];  // N
    int e = in_sizes[8];   // E

    k_init<<<(n + 255) / 256, 256>>>(memb, mids, n);
    k_edge1<<<2048, 256>>>(row, col, e);
    k_scan<<<1, 1024>>>(lambda0, gamma, n, e);
    k_scatter<<<2048, 256>>>(row, col, adj, e);
    k_main<<<(n * 32 + 255) / 256, 256>>>(
        (const float4*)q, (const float4*)k, (const float4*)v, eigs,
        (float4*)d_out, n);
}